// round 10
// baseline (speedup 1.0000x reference)
#include <cuda_runtime.h>
#include <cstdint>

#define N_SAMPLES 2048
#define N_CHAN    512
#define HW        49
#define N_GROUPS  64
#define CHB       32                        // channels per chunk (strip 6272B, 128B-aligned)
#define QCH       (N_CHAN / CHB)            // 16
#define WSZ       16                        // max members per window
#define WMAX      192                       // >= sum ceil(cnt_g/16) worst case (128+64)
#define GRID_B    (WMAX * QCH)              // 3072
#define THREADS   256
#define STRIP_F4  392                       // CHB*HW/4
#define SAMPLE_F4 (N_CHAN * HW / 4)         // 6272

// Persistent scratch (rewritten fully by kernel A every replay).
__device__ unsigned short g_list[N_SAMPLES];  // sample ids sorted by group
__device__ int            g_wtab[WMAX];       // packed {start:11, len:5, g:6}
__device__ float          g_recip[N_GROUPS];

// ---------------------------------------------------------------------------
// Kernel A: CTA 0 counting-sorts idx and builds the window table + recip;
// CTAs 1..64 zero the output (required for prescaled atomic accumulation).
// ---------------------------------------------------------------------------
__global__ __launch_bounds__(THREADS) void prep_kernel(
    const int* __restrict__ idx, float* __restrict__ out)
{
    const int tid = threadIdx.x;

    if (blockIdx.x > 0) {                       // zero out slice (64 CTAs)
        float4* o4 = (float4*)(out + (blockIdx.x - 1) * N_CHAN);
        if (tid < N_CHAN / 4) o4[tid] = make_float4(0.f, 0.f, 0.f, 0.f);
        return;
    }

    __shared__ int h[N_GROUPS];                 // group counts
    __shared__ int off[N_GROUPS];               // scatter cursors
    __shared__ int start_s[N_GROUPS];

    if (tid < N_GROUPS) h[tid] = 0;
    __syncthreads();

    for (int i = tid; i < N_SAMPLES; i += THREADS)
        atomicAdd(&h[idx[i]], 1);
    __syncthreads();

    if (tid == 0) {                             // serial prefix over 64 groups
        int base = 0;
        for (int g = 0; g < N_GROUPS; g++) {
            start_s[g] = base;
            off[g]     = base;
            base      += h[g];
        }
    }
    __syncthreads();

    for (int i = tid; i < N_SAMPLES; i += THREADS) {
        int p = atomicAdd(&off[idx[i]], 1);
        g_list[p] = (unsigned short)i;
    }

    if (tid < N_GROUPS)
        g_recip[tid] = 1.0f / ((float)h[tid] * (float)HW);

    __syncthreads();
    if (tid == 0) {                             // emit single-group windows
        int w = 0;
        for (int g = 0; g < N_GROUPS; g++) {
            int s = start_s[g], c = h[g];
            while (c > 0) {
                int l = c < WSZ ? c : WSZ;
                g_wtab[w++] = s | (l << 11) | (g << 16);
                s += l; c -= l;
            }
        }
        for (; w < WMAX; w++) g_wtab[w] = 0;    // len=0 sentinel
    }
}

// ---------------------------------------------------------------------------
// Kernel B: CTA = (window w, 32-channel chunk q). Streams <=16 members'
// 6272-byte 128B-aligned strips via front-batched LDG.128 into register
// accumulators, reduces to 32 channel sums, prescaled atomicAdd into out.
// ---------------------------------------------------------------------------
__global__ __launch_bounds__(THREADS) void stream_kernel(
    const float* __restrict__ x, float* __restrict__ out)
{
    __shared__ float4 red4[STRIP_F4];           // 6272 B partials

    const int q   = blockIdx.x & (QCH - 1);
    const int w   = blockIdx.x >> 4;
    const int tid = threadIdx.x;

    const int e   = g_wtab[w];
    const int len = (e >> 11) & 31;
    if (len == 0) return;
    const int start = e & 2047;
    const int g     = e >> 16;

    const float4* __restrict__ xq = (const float4*)x + (size_t)q * STRIP_F4;
    const bool hi = (tid < STRIP_F4 - THREADS);   // tid < 136: second f4

    float4 a0 = make_float4(0.f, 0.f, 0.f, 0.f);
    float4 a1 = make_float4(0.f, 0.f, 0.f, 0.f);

    int i = 0;
    for (; i + 4 <= len; i += 4) {              // 4 members front-batched
        const float4* b0 = xq + (size_t)g_list[start + i + 0] * SAMPLE_F4;
        const float4* b1 = xq + (size_t)g_list[start + i + 1] * SAMPLE_F4;
        const float4* b2 = xq + (size_t)g_list[start + i + 2] * SAMPLE_F4;
        const float4* b3 = xq + (size_t)g_list[start + i + 3] * SAMPLE_F4;
        float4 v0 = __ldg(b0 + tid);
        float4 v1 = __ldg(b1 + tid);
        float4 v2 = __ldg(b2 + tid);
        float4 v3 = __ldg(b3 + tid);
        float4 u0, u1, u2, u3;
        if (hi) {
            u0 = __ldg(b0 + THREADS + tid);
            u1 = __ldg(b1 + THREADS + tid);
            u2 = __ldg(b2 + THREADS + tid);
            u3 = __ldg(b3 + THREADS + tid);
        }
        a0.x += v0.x + v1.x + v2.x + v3.x;
        a0.y += v0.y + v1.y + v2.y + v3.y;
        a0.z += v0.z + v1.z + v2.z + v3.z;
        a0.w += v0.w + v1.w + v2.w + v3.w;
        if (hi) {
            a1.x += u0.x + u1.x + u2.x + u3.x;
            a1.y += u0.y + u1.y + u2.y + u3.y;
            a1.z += u0.z + u1.z + u2.z + u3.z;
            a1.w += u0.w + u1.w + u2.w + u3.w;
        }
    }
    for (; i < len; i++) {                      // tail members
        const float4* b = xq + (size_t)g_list[start + i] * SAMPLE_F4;
        float4 v = __ldg(b + tid);
        a0.x += v.x; a0.y += v.y; a0.z += v.z; a0.w += v.w;
        if (hi) {
            float4 u = __ldg(b + THREADS + tid);
            a1.x += u.x; a1.y += u.y; a1.z += u.z; a1.w += u.w;
        }
    }

    red4[tid] = a0;
    if (hi) red4[THREADS + tid] = a1;
    __syncthreads();

    // 1568 floats -> 32 channel sums (stride 49: odd => conflict-free)
    if (tid < CHB) {
        const float* __restrict__ r = (const float*)red4 + tid * HW;
        float s = 0.f;
        #pragma unroll
        for (int k = 0; k < HW; k++) s += r[k];
        atomicAdd(&out[g * N_CHAN + q * CHB + tid], s * __ldg(&g_recip[g]));
    }
}

extern "C" void kernel_launch(void* const* d_in, const int* in_sizes, int n_in,
                              void* d_out, int out_size)
{
    const float* x   = (const float*)d_in[0];
    const int*   idx = (const int*)d_in[1];
    float*       out = (float*)d_out;

    (void)in_sizes; (void)n_in; (void)out_size;

    prep_kernel<<<N_GROUPS + 1, THREADS>>>(idx, out);
    stream_kernel<<<GRID_B, THREADS>>>(x, out);
}

// round 11
// speedup vs baseline: 1.0074x; 1.0074x over previous
#include <cuda_runtime.h>
#include <cstdint>

#define N_SAMPLES 2048
#define N_CHAN    512
#define HW        49
#define N_GROUPS  64
#define CHB       32                        // channels/chunk: strip 6272B, 128B-aligned
#define QCH       (N_CHAN / CHB)            // 16
#define WSZ       16                        // members per window slot
#define WPG       8                         // window slots per group (slot 7 = remainder)
#define GRID_B    (N_GROUPS * WPG * QCH)    // 8192
#define THREADS   256
#define STRIP_F4  392                       // CHB*HW/4
#define SAMPLE_F4 (N_CHAN * HW / 4)         // 6272
#define LCAP      N_SAMPLES                 // per-group row capacity (any distribution)

// Rewritten fully by prep every replay.
__device__ unsigned short g_list[N_GROUPS][LCAP];   // 256 KB
__device__ int            g_cnt[N_GROUPS];
__device__ float          g_recip[N_GROUPS];

// ---------------------------------------------------------------------------
// Prep: one CTA per group. Scan idx, compact this group's members into its
// fixed row, publish cnt + recip, zero this group's out row. Fully parallel.
// ---------------------------------------------------------------------------
__global__ __launch_bounds__(THREADS) void prep_kernel(
    const int* __restrict__ idx, float* __restrict__ out)
{
    __shared__ unsigned short sl[N_SAMPLES];
    __shared__ int s_cnt;

    const int g   = blockIdx.x;
    const int tid = threadIdx.x;

    if (tid == 0) s_cnt = 0;
    __syncthreads();

    const int4* __restrict__ idx4 = (const int4*)idx;
    for (int i = tid; i < N_SAMPLES / 4; i += THREADS) {
        int4 v = idx4[i];
        int  b = 4 * i;
        if (v.x == g) sl[atomicAdd(&s_cnt, 1)] = (unsigned short)(b + 0);
        if (v.y == g) sl[atomicAdd(&s_cnt, 1)] = (unsigned short)(b + 1);
        if (v.z == g) sl[atomicAdd(&s_cnt, 1)] = (unsigned short)(b + 2);
        if (v.w == g) sl[atomicAdd(&s_cnt, 1)] = (unsigned short)(b + 3);
    }
    __syncthreads();
    const int cnt = s_cnt;

    for (int i = tid; i < cnt; i += THREADS) g_list[g][i] = sl[i];

    if (tid == 0) {
        g_cnt[g]   = cnt;
        g_recip[g] = 1.0f / ((float)cnt * (float)HW);
    }

    // zero this group's output row (atomic accumulation target)
    float4* o4 = (float4*)(out + g * N_CHAN);
    if (tid < N_CHAN / 4) o4[tid] = make_float4(0.f, 0.f, 0.f, 0.f);
}

// ---------------------------------------------------------------------------
// Stream: CTA = (group g, window slot, 32-channel chunk q). Streams <=16
// members' 6272-byte 128B-aligned strips via front-batched LDG.128 into
// register accumulators, reduces to 32 channel sums, prescaled atomicAdd.
// ---------------------------------------------------------------------------
__global__ __launch_bounds__(THREADS, 6) void stream_kernel(
    const float* __restrict__ x, float* __restrict__ out)
{
    __shared__ float4 red4[STRIP_F4];           // 6272 B partials

    const int q    = blockIdx.x & (QCH - 1);
    const int slot = (blockIdx.x >> 4) & (WPG - 1);
    const int g    = blockIdx.x >> 7;
    const int tid  = threadIdx.x;

    const int cnt   = g_cnt[g];
    const int start = slot * WSZ;
    int len = cnt - start;
    if (len <= 0) return;
    if (slot < WPG - 1 && len > WSZ) len = WSZ;   // last slot takes remainder

    const unsigned short* __restrict__ lst = &g_list[g][start];
    const float4* __restrict__ xq = (const float4*)x + (size_t)q * STRIP_F4;
    const bool hi = (tid < STRIP_F4 - THREADS);   // tid < 136: second f4

    float4 a0 = make_float4(0.f, 0.f, 0.f, 0.f);
    float4 a1 = make_float4(0.f, 0.f, 0.f, 0.f);

    int i = 0;
    for (; i + 4 <= len; i += 4) {               // 4 members front-batched
        const float4* b0 = xq + (size_t)lst[i + 0] * SAMPLE_F4;
        const float4* b1 = xq + (size_t)lst[i + 1] * SAMPLE_F4;
        const float4* b2 = xq + (size_t)lst[i + 2] * SAMPLE_F4;
        const float4* b3 = xq + (size_t)lst[i + 3] * SAMPLE_F4;
        float4 v0 = __ldg(b0 + tid);
        float4 v1 = __ldg(b1 + tid);
        float4 v2 = __ldg(b2 + tid);
        float4 v3 = __ldg(b3 + tid);
        float4 u0, u1, u2, u3;
        if (hi) {
            u0 = __ldg(b0 + THREADS + tid);
            u1 = __ldg(b1 + THREADS + tid);
            u2 = __ldg(b2 + THREADS + tid);
            u3 = __ldg(b3 + THREADS + tid);
        }
        a0.x += v0.x + v1.x + v2.x + v3.x;
        a0.y += v0.y + v1.y + v2.y + v3.y;
        a0.z += v0.z + v1.z + v2.z + v3.z;
        a0.w += v0.w + v1.w + v2.w + v3.w;
        if (hi) {
            a1.x += u0.x + u1.x + u2.x + u3.x;
            a1.y += u0.y + u1.y + u2.y + u3.y;
            a1.z += u0.z + u1.z + u2.z + u3.z;
            a1.w += u0.w + u1.w + u2.w + u3.w;
        }
    }
    for (; i < len; i++) {                       // tail members
        const float4* b = xq + (size_t)lst[i] * SAMPLE_F4;
        float4 v = __ldg(b + tid);
        a0.x += v.x; a0.y += v.y; a0.z += v.z; a0.w += v.w;
        if (hi) {
            float4 u = __ldg(b + THREADS + tid);
            a1.x += u.x; a1.y += u.y; a1.z += u.z; a1.w += u.w;
        }
    }

    red4[tid] = a0;
    if (hi) red4[THREADS + tid] = a1;
    __syncthreads();

    // 1568 floats -> 32 channel sums (stride 49: odd => conflict-free)
    if (tid < CHB) {
        const float* __restrict__ r = (const float*)red4 + tid * HW;
        float s = 0.f;
        #pragma unroll
        for (int k = 0; k < HW; k++) s += r[k];
        atomicAdd(&out[g * N_CHAN + q * CHB + tid], s * g_recip[g]);
    }
}

extern "C" void kernel_launch(void* const* d_in, const int* in_sizes, int n_in,
                              void* d_out, int out_size)
{
    const float* x   = (const float*)d_in[0];
    const int*   idx = (const int*)d_in[1];
    float*       out = (float*)d_out;

    (void)in_sizes; (void)n_in; (void)out_size;

    prep_kernel<<<N_GROUPS, THREADS>>>(idx, out);
    stream_kernel<<<GRID_B, THREADS>>>(x, out);
}

// round 12
// speedup vs baseline: 1.0885x; 1.0805x over previous
#include <cuda_runtime.h>
#include <cstdint>

#define N_SAMPLES 2048
#define N_CHAN    512
#define HW        49
#define N_GROUPS  64
#define CHB       32                        // channels/chunk: strip 6272B, 128B-aligned
#define QCH       (N_CHAN / CHB)            // 16
#define WSZ       16                        // members per window slot
#define WPG       4                         // slots per group (slot 3 = remainder)
#define GRID_B    (N_GROUPS * WPG * QCH)    // 4096
#define THREADS   256
#define STRIP_F4  392                       // CHB*HW/4
#define SAMPLE_F4 (N_CHAN * HW / 4)         // 6272

// Rewritten fully by prep every replay.
__device__ unsigned short g_list[N_GROUPS][N_SAMPLES];   // 256 KB
__device__ int            g_cnt[N_GROUPS];
__device__ float          g_recip[N_GROUPS];

// ---------------------------------------------------------------------------
// Prep: one CTA per group. Scan idx, compact this group's members into its
// fixed row, publish cnt + recip, zero this group's out row. Fully parallel.
// ---------------------------------------------------------------------------
__global__ __launch_bounds__(THREADS) void prep_kernel(
    const int* __restrict__ idx, float* __restrict__ out)
{
    __shared__ unsigned short sl[N_SAMPLES];
    __shared__ int s_cnt;

    const int g   = blockIdx.x;
    const int tid = threadIdx.x;

    if (tid == 0) s_cnt = 0;
    __syncthreads();

    const int4* __restrict__ idx4 = (const int4*)idx;
    for (int i = tid; i < N_SAMPLES / 4; i += THREADS) {
        int4 v = idx4[i];
        int  b = 4 * i;
        if (v.x == g) sl[atomicAdd(&s_cnt, 1)] = (unsigned short)(b + 0);
        if (v.y == g) sl[atomicAdd(&s_cnt, 1)] = (unsigned short)(b + 1);
        if (v.z == g) sl[atomicAdd(&s_cnt, 1)] = (unsigned short)(b + 2);
        if (v.w == g) sl[atomicAdd(&s_cnt, 1)] = (unsigned short)(b + 3);
    }
    __syncthreads();
    const int cnt = s_cnt;

    for (int i = tid; i < cnt; i += THREADS) g_list[g][i] = sl[i];

    if (tid == 0) {
        g_cnt[g]   = cnt;
        g_recip[g] = 1.0f / ((float)cnt * (float)HW);
    }

    // zero this group's output row (atomic accumulation target)
    float4* o4 = (float4*)(out + g * N_CHAN);
    if (tid < N_CHAN / 4) o4[tid] = make_float4(0.f, 0.f, 0.f, 0.f);
}

// ---------------------------------------------------------------------------
// Stream: CTA = (group g, window slot, 32-channel chunk q; q fastest so the
// 16 CTAs of a window stream whole sample rows together). Streams <=16
// members' 6272-byte 128B-aligned strips via front-batched LDG.128 into
// register accumulators, reduces to 32 channel sums, prescaled atomicAdd.
// NO occupancy clamp: full register budget keeps the 8-load batch intact.
// ---------------------------------------------------------------------------
__global__ __launch_bounds__(THREADS) void stream_kernel(
    const float* __restrict__ x, float* __restrict__ out)
{
    __shared__ float4 red4[STRIP_F4];           // 6272 B partials

    const int q    = blockIdx.x & (QCH - 1);
    const int slot = (blockIdx.x >> 4) & (WPG - 1);
    const int g    = blockIdx.x >> 6;
    const int tid  = threadIdx.x;

    const int cnt   = g_cnt[g];
    const int start = slot * WSZ;
    int len = cnt - start;
    if (len <= 0) return;
    if (slot < WPG - 1 && len > WSZ) len = WSZ;   // last slot takes remainder

    const unsigned short* __restrict__ lst = &g_list[g][start];
    const float4* __restrict__ xq = (const float4*)x + (size_t)q * STRIP_F4;
    const bool hi = (tid < STRIP_F4 - THREADS);   // tid < 136: second f4

    float4 a0 = make_float4(0.f, 0.f, 0.f, 0.f);
    float4 a1 = make_float4(0.f, 0.f, 0.f, 0.f);

    int i = 0;
    for (; i + 4 <= len; i += 4) {               // 4 members front-batched
        const float4* b0 = xq + (size_t)lst[i + 0] * SAMPLE_F4;
        const float4* b1 = xq + (size_t)lst[i + 1] * SAMPLE_F4;
        const float4* b2 = xq + (size_t)lst[i + 2] * SAMPLE_F4;
        const float4* b3 = xq + (size_t)lst[i + 3] * SAMPLE_F4;
        float4 v0 = __ldg(b0 + tid);
        float4 v1 = __ldg(b1 + tid);
        float4 v2 = __ldg(b2 + tid);
        float4 v3 = __ldg(b3 + tid);
        float4 u0, u1, u2, u3;
        if (hi) {
            u0 = __ldg(b0 + THREADS + tid);
            u1 = __ldg(b1 + THREADS + tid);
            u2 = __ldg(b2 + THREADS + tid);
            u3 = __ldg(b3 + THREADS + tid);
        }
        a0.x += v0.x + v1.x + v2.x + v3.x;
        a0.y += v0.y + v1.y + v2.y + v3.y;
        a0.z += v0.z + v1.z + v2.z + v3.z;
        a0.w += v0.w + v1.w + v2.w + v3.w;
        if (hi) {
            a1.x += u0.x + u1.x + u2.x + u3.x;
            a1.y += u0.y + u1.y + u2.y + u3.y;
            a1.z += u0.z + u1.z + u2.z + u3.z;
            a1.w += u0.w + u1.w + u2.w + u3.w;
        }
    }
    for (; i < len; i++) {                       // tail members
        const float4* b = xq + (size_t)lst[i] * SAMPLE_F4;
        float4 v = __ldg(b + tid);
        a0.x += v.x; a0.y += v.y; a0.z += v.z; a0.w += v.w;
        if (hi) {
            float4 u = __ldg(b + THREADS + tid);
            a1.x += u.x; a1.y += u.y; a1.z += u.z; a1.w += u.w;
        }
    }

    red4[tid] = a0;
    if (hi) red4[THREADS + tid] = a1;
    __syncthreads();

    // 1568 floats -> 32 channel sums (stride 49: odd => conflict-free)
    if (tid < CHB) {
        const float* __restrict__ r = (const float*)red4 + tid * HW;
        float s = 0.f;
        #pragma unroll
        for (int k = 0; k < HW; k++) s += r[k];
        atomicAdd(&out[g * N_CHAN + q * CHB + tid], s * g_recip[g]);
    }
}

extern "C" void kernel_launch(void* const* d_in, const int* in_sizes, int n_in,
                              void* d_out, int out_size)
{
    const float* x   = (const float*)d_in[0];
    const int*   idx = (const int*)d_in[1];
    float*       out = (float*)d_out;

    (void)in_sizes; (void)n_in; (void)out_size;

    prep_kernel<<<N_GROUPS, THREADS>>>(idx, out);
    stream_kernel<<<GRID_B, THREADS>>>(x, out);
}